// round 1
// baseline (speedup 1.0000x reference)
#include <cuda_runtime.h>
#include <cuda_bf16.h>
#include <cstdint>

#define BATCH 32
#define SEQ   512
#define DM    1024
#define NSAMP 1000
#define SPAD  1024
#define LDAH  72      // smem tile row stride in halves (64 + 8 pad)
#define LDE   132     // epilogue smem row stride in floats (128 + 4 pad)

// -------- scratch (device globals: allocation-free rule) --------
__device__ __nv_bfloat16 g_Xbf[BATCH*SEQ*DM];        // ~33.5 MB
__device__ __nv_bfloat16 g_Wg [BATCH*SPAD*DM];       // ~67 MB (gathered, padded)
__device__ float g_biasAdj[BATCH*SPAD];
__device__ int   g_sid   [BATCH*SPAD];
__device__ float g_trueAdj[BATCH*SEQ];
__device__ float g_loss  [BATCH*SEQ];

// TF log-uniform expected-count, replicated in f32 exactly like the reference
// (including the log(id+2)-log(id+1) cancellation — reference has it too).
__device__ __forceinline__ float log_q_f(int id){
    float f  = (float)id;
    float p  = (logf(f + 2.0f) - logf(f + 1.0f)) / 10.819798284210285f; // np.log(50001.)
    float t  = 1000.0f * log1pf(-p);
    return logf(-expm1f(t));
}

// -------- kernel 1: X f32 -> bf16 --------
__global__ void k_convx(const float* __restrict__ X){
    int i = blockIdx.x*blockDim.x + threadIdx.x;  // over float4s
    if (i < BATCH*SEQ*DM/4){
        float4 v = ((const float4*)X)[i];
        __nv_bfloat162 p0 = __floats2bfloat162_rn(v.x, v.y);
        __nv_bfloat162 p1 = __floats2bfloat162_rn(v.z, v.w);
        uint2 u; u.x = *(uint32_t*)&p0; u.y = *(uint32_t*)&p1;
        ((uint2*)g_Xbf)[i] = u;
    }
}

// -------- kernel 2: gather W[sampled_ids] -> bf16, plus bias - log_q --------
__global__ void k_gather(const int* __restrict__ samp, const float* __restrict__ W,
                         const float* __restrict__ bias){
    int warp = (blockIdx.x*blockDim.x + threadIdx.x) >> 5;
    int lane = threadIdx.x & 31;
    if (warp >= BATCH*SPAD) return;
    int b = warp >> 10, s = warp & 1023;
    int id = (s < NSAMP) ? samp[b*NSAMP + s] : -1;
    __nv_bfloat16* dst = g_Wg + (size_t)warp*DM;
    if (id >= 0){
        const float4* src = (const float4*)(W + (size_t)id*DM);
        #pragma unroll
        for (int j=0;j<8;j++){
            float4 v = src[lane + j*32];
            __nv_bfloat162 p0 = __floats2bfloat162_rn(v.x, v.y);
            __nv_bfloat162 p1 = __floats2bfloat162_rn(v.z, v.w);
            uint2 u; u.x = *(uint32_t*)&p0; u.y = *(uint32_t*)&p1;
            ((uint2*)dst)[lane + j*32] = u;
        }
        if (lane == 0){ g_biasAdj[warp] = bias[id] - log_q_f(id); g_sid[warp] = id; }
    } else {
        uint2 z = make_uint2(0u,0u);
        #pragma unroll
        for (int j=0;j<8;j++) ((uint2*)dst)[lane + j*32] = z;
        if (lane == 0){ g_biasAdj[warp] = -1.0e30f; g_sid[warp] = -1; }
    }
}

// -------- kernel 3: exact fp32 true logits --------
__global__ void k_true(const float* __restrict__ X, const int* __restrict__ nexts,
                       const float* __restrict__ W, const float* __restrict__ bias){
    int g = blockIdx.x*8 + (threadIdx.x >> 5);
    int lane = threadIdx.x & 31;
    if (g >= BATCH*SEQ) return;
    int id = nexts[g];
    const float4* xr = (const float4*)(X + (size_t)g*DM);
    const float4* wr = (const float4*)(W + (size_t)id*DM);
    float acc = 0.f;
    #pragma unroll
    for (int j=0;j<8;j++){
        float4 a = xr[lane + j*32], w = wr[lane + j*32];
        acc += a.x*w.x + a.y*w.y + a.z*w.z + a.w*w.w;
    }
    #pragma unroll
    for (int off=16; off>0; off>>=1) acc += __shfl_xor_sync(0xffffffffu, acc, off);
    if (lane == 0) g_trueAdj[g] = acc + bias[id] - log_q_f(id);
}

// -------- kernel 4: fused bf16 GEMM (mma.sync) + online logsumexp --------
__device__ __forceinline__ void ld_chunk(__nv_bfloat16* sA, __nv_bfloat16* sB, int buf, int kc,
    const __nv_bfloat16* Ag, const __nv_bfloat16* Bg, int tid){
    __nv_bfloat16* dA = sA + buf*128*LDAH;
    __nv_bfloat16* dB = sB + buf*128*LDAH;
    #pragma unroll
    for (int j=0;j<4;j++){
        int idx = tid + j*256;
        int r = idx >> 3, c8 = idx & 7;
        const __nv_bfloat16* gA = Ag + (size_t)r*DM + kc*64 + c8*8;
        const __nv_bfloat16* gB = Bg + (size_t)r*DM + kc*64 + c8*8;
        uint32_t saA = (uint32_t)__cvta_generic_to_shared(dA + r*LDAH + c8*8);
        uint32_t saB = (uint32_t)__cvta_generic_to_shared(dB + r*LDAH + c8*8);
        asm volatile("cp.async.cg.shared.global [%0],[%1],16;\n" :: "r"(saA), "l"(gA));
        asm volatile("cp.async.cg.shared.global [%0],[%1],16;\n" :: "r"(saB), "l"(gB));
    }
}

__global__ __launch_bounds__(256,1)
void k_main(const int* __restrict__ nexts){
    extern __shared__ char smem[];
    __nv_bfloat16* sA = (__nv_bfloat16*)(smem);             // 2*128*72*2 = 36864
    __nv_bfloat16* sB = (__nv_bfloat16*)(smem + 36864);     // 36864
    float* sEpi  = (float*)(smem + 73728);                  // 128*132*4 = 67584
    float* sBias = (float*)(smem + 141312);                 // 4096
    int*   sSid  = (int*)  (smem + 145408);                 // 4096
    float* sTrue = (float*)(smem + 149504);                 // 512
    float* sM    = (float*)(smem + 150016);                 // 512
    float* sL    = (float*)(smem + 150528);                 // 512
    int*   sTid  = (int*)  (smem + 151040);                 // 512  -> total 151552

    int cta = blockIdx.x;
    int b = cta >> 2;
    int row0 = (cta & 3) * 128;
    int tid = threadIdx.x, warp = tid >> 5, lane = tid & 31;

    for (int i=tid; i<SPAD; i+=256){ sBias[i] = g_biasAdj[b*SPAD+i]; sSid[i] = g_sid[b*SPAD+i]; }
    for (int i=tid; i<128; i+=256){
        float ta = g_trueAdj[b*SEQ + row0 + i];
        sTrue[i] = ta; sM[i] = ta; sL[i] = 1.0f;
        sTid[i] = nexts[b*SEQ + row0 + i];
    }
    __syncthreads();

    const __nv_bfloat16* Ag    = g_Xbf + (size_t)(b*SEQ + row0)*DM;
    const __nv_bfloat16* Bbase = g_Wg  + (size_t)b*SPAD*DM;

    int m0 = (warp >> 1) * 32, n0 = (warp & 1) * 64;

    for (int nc=0; nc<8; nc++){
        const __nv_bfloat16* Bg = Bbase + (size_t)(nc*128)*DM;
        float acc[2][8][4];
        #pragma unroll
        for (int i=0;i<2;i++)
        #pragma unroll
        for (int j=0;j<8;j++)
        #pragma unroll
        for (int k=0;k<4;k++) acc[i][j][k] = 0.f;

        ld_chunk(sA, sB, 0, 0, Ag, Bg, tid);
        asm volatile("cp.async.commit_group;\n");

        for (int kc=0; kc<16; kc++){
            int cur = kc & 1;
            if (kc+1 < 16){
                ld_chunk(sA, sB, cur^1, kc+1, Ag, Bg, tid);
                asm volatile("cp.async.commit_group;\n");
                asm volatile("cp.async.wait_group 1;\n");
            } else {
                asm volatile("cp.async.wait_group 0;\n");
            }
            __syncthreads();
            const __nv_bfloat16* A = sA + cur*128*LDAH;
            const __nv_bfloat16* B = sB + cur*128*LDAH;
            #pragma unroll
            for (int kk=0; kk<4; kk++){
                uint32_t a[2][4];
                #pragma unroll
                for (int t=0;t<2;t++){
                    const __nv_bfloat16* p = A + (m0 + t*16 + (lane & 15))*LDAH + kk*16 + (lane >> 4)*8;
                    uint32_t sa = (uint32_t)__cvta_generic_to_shared(p);
                    asm volatile("ldmatrix.sync.aligned.m8n8.x4.shared.b16 {%0,%1,%2,%3},[%4];\n"
                        : "=r"(a[t][0]), "=r"(a[t][1]), "=r"(a[t][2]), "=r"(a[t][3]) : "r"(sa));
                }
                uint32_t bb[8][2];
                #pragma unroll
                for (int j=0;j<8;j+=2){
                    const __nv_bfloat16* p = B + (n0 + j*8 + (lane & 7) + (lane >> 4)*8)*LDAH
                                               + kk*16 + ((lane >> 3) & 1)*8;
                    uint32_t sb = (uint32_t)__cvta_generic_to_shared(p);
                    asm volatile("ldmatrix.sync.aligned.m8n8.x4.shared.b16 {%0,%1,%2,%3},[%4];\n"
                        : "=r"(bb[j][0]), "=r"(bb[j][1]), "=r"(bb[j+1][0]), "=r"(bb[j+1][1]) : "r"(sb));
                }
                #pragma unroll
                for (int t=0;t<2;t++)
                #pragma unroll
                for (int j=0;j<8;j++){
                    asm volatile("mma.sync.aligned.m16n8k16.row.col.f32.bf16.bf16.f32 "
                        "{%0,%1,%2,%3},{%4,%5,%6,%7},{%8,%9},{%0,%1,%2,%3};\n"
                        : "+f"(acc[t][j][0]), "+f"(acc[t][j][1]), "+f"(acc[t][j][2]), "+f"(acc[t][j][3])
                        : "r"(a[t][0]), "r"(a[t][1]), "r"(a[t][2]), "r"(a[t][3]),
                          "r"(bb[j][0]), "r"(bb[j][1]));
                }
            }
            __syncthreads();
        }

        // epilogue: stash chunk logits, then per-row online logsumexp
        #pragma unroll
        for (int t=0;t<2;t++)
        #pragma unroll
        for (int j=0;j<8;j++){
            int r = m0 + t*16 + (lane >> 2);
            int c = n0 + j*8 + (lane & 3)*2;
            sEpi[r*LDE + c]       = acc[t][j][0];
            sEpi[r*LDE + c + 1]   = acc[t][j][1];
            sEpi[(r+8)*LDE + c]   = acc[t][j][2];
            sEpi[(r+8)*LDE + c+1] = acc[t][j][3];
        }
        __syncthreads();

        for (int rr=0; rr<16; rr++){
            int row = warp*16 + rr;
            int tv = sTid[row];
            float v[4]; float mx = -3.0e38f;
            #pragma unroll
            for (int q=0;q<4;q++){
                int col = lane + q*32;
                int g = nc*128 + col;
                float val = sEpi[row*LDE + col] + sBias[g];
                if (sSid[g] == tv) val = -1e9f;     // accidental-hit removal
                v[q] = val; mx = fmaxf(mx, val);
            }
            #pragma unroll
            for (int off=16; off>0; off>>=1) mx = fmaxf(mx, __shfl_xor_sync(0xffffffffu, mx, off));
            float mOld = sM[row];
            float mNew = fmaxf(mOld, mx);
            float s = 0.f;
            #pragma unroll
            for (int q=0;q<4;q++) s += __expf(v[q] - mNew);
            #pragma unroll
            for (int off=16; off>0; off>>=1) s += __shfl_xor_sync(0xffffffffu, s, off);
            if (lane == 0){ sL[row] = sL[row]*__expf(mOld - mNew) + s; sM[row] = mNew; }
        }
        __syncthreads();
    }

    for (int i=tid; i<128; i+=256)
        g_loss[b*SEQ + row0 + i] = logf(sL[i]) + sM[i] - sTrue[i];
}

// -------- kernel 5: mean --------
__global__ void k_final(float* out){
    __shared__ float ss[256];
    float s = 0.f;
    for (int i=threadIdx.x; i<BATCH*SEQ; i+=256) s += g_loss[i];
    ss[threadIdx.x] = s; __syncthreads();
    for (int o=128; o>0; o>>=1){
        if (threadIdx.x < o) ss[threadIdx.x] += ss[threadIdx.x + o];
        __syncthreads();
    }
    if (threadIdx.x == 0) out[0] = 0.5f * ss[0] / (float)(BATCH*SEQ);
}

extern "C" void kernel_launch(void* const* d_in, const int* in_sizes, int n_in,
                              void* d_out, int out_size){
    const float* X     = (const float*)d_in[0];
    const int*   nexts = (const int*)  d_in[1];
    const int*   samp  = (const int*)  d_in[2];
    const float* W     = (const float*)d_in[3];
    const float* bias  = (const float*)d_in[4];
    float* out = (float*)d_out;

    cudaFuncSetAttribute(k_main, cudaFuncAttributeMaxDynamicSharedMemorySize, 151552);

    k_convx <<<BATCH*SEQ*DM/4/256, 256>>>(X);
    k_gather<<<BATCH*SPAD/8,       256>>>(samp, W, bias);
    k_true  <<<BATCH*SEQ/8,        256>>>(X, nexts, W, bias);
    k_main  <<<BATCH*4, 256, 151552>>>(nexts);
    k_final <<<1, 256>>>(out);
}

// round 4
// speedup vs baseline: 1.2752x; 1.2752x over previous
#include <cuda_runtime.h>
#include <cuda_bf16.h>
#include <cstdint>

#define BATCH 32
#define SEQ   512
#define DM    1024
#define NSAMP 1000
#define SPAD  1024
#define LDAH  72                 // smem row stride in halves (64 + 8 pad)
#define STAGE_BYTES 36864        // (128 A rows + 128 B rows) * 72 halves * 2B
#define NSTG  3
#define OFF_BIAS (NSTG*STAGE_BYTES)       // 110592
#define OFF_SID  (OFF_BIAS + 4096)        // 114688
#define OFF_MM   (OFF_SID  + 4096)        // 118784  float[2][128]
#define OFF_LL   (OFF_MM   + 1024)        // 119808  float[2][128]
#define SMEM_REQ (OFF_LL + 1024)          // 120832

// ---------------- scratch (device globals; allocation-free rule) ----------------
__device__ __nv_bfloat16 g_Xbf[BATCH*SEQ*DM];
__device__ __nv_bfloat16 g_Wg [BATCH*SPAD*DM];
__device__ float g_biasAdj[BATCH*SPAD];
__device__ int   g_sid   [BATCH*SPAD];
__device__ float g_trueAdj[BATCH*SEQ];
__device__ float g_loss  [BATCH*SEQ];

__device__ __forceinline__ float log_q_f(int id){
    float f = (float)id;
    float p = (logf(f + 2.0f) - logf(f + 1.0f)) / 10.819798284210285f; // log(50001)
    float t = 1000.0f * log1pf(-p);
    return logf(-expm1f(t));
}

// ---------------- prelude: gather W rows -> bf16  +  exact f32 true logits + X->bf16 ----------------
__global__ void k_prep(const float* __restrict__ X, const int* __restrict__ nexts,
                       const int* __restrict__ samp, const float* __restrict__ W,
                       const float* __restrict__ bias){
    int lane = threadIdx.x & 31;
    if (blockIdx.x < 4096){
        // gather: one warp per sampled row (padded to SPAD)
        int warp = (blockIdx.x*blockDim.x + threadIdx.x) >> 5;
        int b = warp >> 10, s = warp & 1023;
        int id = (s < NSAMP) ? samp[b*NSAMP + s] : -1;
        __nv_bfloat16* dst = g_Wg + (size_t)warp*DM;
        if (id >= 0){
            const float4* src = (const float4*)(W + (size_t)id*DM);
            #pragma unroll
            for (int j=0;j<8;j++){
                float4 v = src[lane + j*32];
                __nv_bfloat162 p0 = __floats2bfloat162_rn(v.x, v.y);
                __nv_bfloat162 p1 = __floats2bfloat162_rn(v.z, v.w);
                uint2 u; u.x = *(uint32_t*)&p0; u.y = *(uint32_t*)&p1;
                ((uint2*)dst)[lane + j*32] = u;
            }
            if (lane == 0){ g_biasAdj[warp] = bias[id] - log_q_f(id); g_sid[warp] = id; }
        } else {
            uint2 z = make_uint2(0u,0u);
            #pragma unroll
            for (int j=0;j<8;j++) ((uint2*)dst)[lane + j*32] = z;
            if (lane == 0){ g_biasAdj[warp] = -1.0e30f; g_sid[warp] = -1; }
        }
    } else {
        // true logit (exact fp32) + X conversion
        int g = (blockIdx.x - 4096)*8 + (threadIdx.x >> 5);
        int id = nexts[g];
        const float4* xr = (const float4*)(X + (size_t)g*DM);
        const float4* wr = (const float4*)(W + (size_t)id*DM);
        uint2* xo = (uint2*)(g_Xbf + (size_t)g*DM);
        float acc = 0.f;
        #pragma unroll
        for (int j=0;j<8;j++){
            float4 a = xr[lane + j*32], w = wr[lane + j*32];
            acc += a.x*w.x + a.y*w.y + a.z*w.z + a.w*w.w;
            __nv_bfloat162 p0 = __floats2bfloat162_rn(a.x, a.y);
            __nv_bfloat162 p1 = __floats2bfloat162_rn(a.z, a.w);
            uint2 u; u.x = *(uint32_t*)&p0; u.y = *(uint32_t*)&p1;
            xo[lane + j*32] = u;
        }
        #pragma unroll
        for (int off=16; off>0; off>>=1) acc += __shfl_xor_sync(0xffffffffu, acc, off);
        if (lane == 0) g_trueAdj[g] = acc + bias[id] - log_q_f(id);
    }
}

// ---------------- main: mma.sync GEMM + fragment-local online logsumexp ----------------
// grid 128 (4 CTAs/batch, M=128). 8 warps, 4x2 warp grid of 32x64 tiles, N-chunk=128.
// K pipelined: 3-stage cp.async ring, K-chunk=64, 128 total stages (8 nc * 16 kc).
__device__ __forceinline__ void issue_stage(uint32_t sbase, int it,
    const __nv_bfloat16* Ag, const __nv_bfloat16* Bb, int tid){
    if (it < 128){
        int nc = it >> 4, kc = it & 15;
        uint32_t st = sbase + (uint32_t)(it % NSTG)*STAGE_BYTES;
        const __nv_bfloat16* gA = Ag + kc*64;
        const __nv_bfloat16* gB = Bb + (size_t)(nc*128)*DM + kc*64;
        #pragma unroll
        for (int i=0;i<4;i++){
            int gi = tid + i*256; int r = gi>>3, c8 = gi&7;
            uint32_t dst = st + (uint32_t)(r*(LDAH*2) + c8*16);
            const void* src = gA + (size_t)r*DM + c8*8;
            asm volatile("cp.async.cg.shared.global [%0],[%1],16;" :: "r"(dst), "l"(src));
        }
        #pragma unroll
        for (int i=0;i<4;i++){
            int gi = tid + i*256; int r = gi>>3, c8 = gi&7;
            uint32_t dst = st + (uint32_t)(128*(LDAH*2) + r*(LDAH*2) + c8*16);
            const void* src = gB + (size_t)r*DM + c8*8;
            asm volatile("cp.async.cg.shared.global [%0],[%1],16;" :: "r"(dst), "l"(src));
        }
    }
    asm volatile("cp.async.commit_group;");
}

__global__ __launch_bounds__(256,1)
void k_main(const int* __restrict__ nexts){
    extern __shared__ char smraw[];
    char* p = smraw;
    const uint32_t sbase = (uint32_t)__cvta_generic_to_shared(p);
    float* sBias = (float*)(p + OFF_BIAS);
    int*   sSid  = (int*)  (p + OFF_SID);
    float* sMM   = (float*)(p + OFF_MM);
    float* sLL   = (float*)(p + OFF_LL);

    int tid = threadIdx.x, warp = tid >> 5, lane = tid & 31;
    int cta = blockIdx.x, b = cta >> 2, row0 = (cta & 3) << 7;
    int m0 = (warp >> 1) * 32, n0 = (warp & 1) * 64;

    for (int i=tid; i<SPAD; i+=256){ sBias[i] = g_biasAdj[b*SPAD+i]; sSid[i] = g_sid[b*SPAD+i]; }

    const __nv_bfloat16* Ag = g_Xbf + (size_t)(b*SEQ + row0)*DM;
    const __nv_bfloat16* Bb = g_Wg  + (size_t)b*SPAD*DM;

    // true ids for this thread's 4 rows (t*16 + h*8 + lane>>2 within warp tile)
    int tv[4];
    #pragma unroll
    for (int i=0;i<4;i++){
        int t = i>>1, h = i&1;
        tv[i] = nexts[b*SEQ + row0 + m0 + t*16 + h*8 + (lane>>2)];
    }
    float m[4], l[4];
    #pragma unroll
    for (int i=0;i<4;i++){ m[i] = -3.0e38f; l[i] = 0.f; }

    issue_stage(sbase, 0, Ag, Bb, tid);
    issue_stage(sbase, 1, Ag, Bb, tid);

    float acc[2][8][4];
    for (int it=0; it<128; ++it){
        int nc = it >> 4, kc = it & 15;
        asm volatile("cp.async.wait_group 1;");
        __syncthreads();
        issue_stage(sbase, it+2, Ag, Bb, tid);

        if (kc == 0){
            #pragma unroll
            for (int t=0;t<2;t++)
            #pragma unroll
            for (int j=0;j<8;j++)
            #pragma unroll
            for (int k=0;k<4;k++) acc[t][j][k] = 0.f;
        }

        char* st = p + (it % NSTG)*STAGE_BYTES;
        const __nv_bfloat16* A = (const __nv_bfloat16*)st;
        const __nv_bfloat16* B = (const __nv_bfloat16*)(st + 128*LDAH*2);
        #pragma unroll
        for (int kk=0; kk<4; kk++){
            uint32_t a[2][4];
            #pragma unroll
            for (int t=0;t<2;t++){
                const __nv_bfloat16* q = A + (m0 + t*16 + (lane & 15))*LDAH + kk*16 + (lane >> 4)*8;
                uint32_t sa = (uint32_t)__cvta_generic_to_shared(q);
                asm volatile("ldmatrix.sync.aligned.m8n8.x4.shared.b16 {%0,%1,%2,%3},[%4];"
                    : "=r"(a[t][0]), "=r"(a[t][1]), "=r"(a[t][2]), "=r"(a[t][3]) : "r"(sa));
            }
            uint32_t bb[8][2];
            #pragma unroll
            for (int j=0;j<8;j+=2){
                const __nv_bfloat16* q = B + (n0 + j*8 + (lane & 7) + (lane >> 4)*8)*LDAH
                                           + kk*16 + ((lane >> 3) & 1)*8;
                uint32_t sb = (uint32_t)__cvta_generic_to_shared(q);
                asm volatile("ldmatrix.sync.aligned.m8n8.x4.shared.b16 {%0,%1,%2,%3},[%4];"
                    : "=r"(bb[j][0]), "=r"(bb[j][1]), "=r"(bb[j+1][0]), "=r"(bb[j+1][1]) : "r"(sb));
            }
            #pragma unroll
            for (int t=0;t<2;t++)
            #pragma unroll
            for (int j=0;j<8;j++){
                asm volatile("mma.sync.aligned.m16n8k16.row.col.f32.bf16.bf16.f32 "
                    "{%0,%1,%2,%3},{%4,%5,%6,%7},{%8,%9},{%0,%1,%2,%3};"
                    : "+f"(acc[t][j][0]), "+f"(acc[t][j][1]), "+f"(acc[t][j][2]), "+f"(acc[t][j][3])
                    : "r"(a[t][0]), "r"(a[t][1]), "r"(a[t][2]), "r"(a[t][3]),
                      "r"(bb[j][0]), "r"(bb[j][1]));
            }
        }

        if (kc == 15){
            // fragment-local online logsumexp over this 128-col chunk
            int cbase = nc*128 + n0 + (lane & 3)*2;
            #pragma unroll
            for (int t=0;t<2;t++)
            #pragma unroll
            for (int h=0;h<2;h++){
                int ri = t*2 + h;
                float bm = -3.0e38f;
                #pragma unroll
                for (int j=0;j<8;j++){
                    int c = cbase + j*8;
                    float2 bi = *(const float2*)&sBias[c];
                    int2   si = *(const int2*)  &sSid[c];
                    float v0 = acc[t][j][2*h]   + bi.x; if (si.x == tv[ri]) v0 = -1.0e9f;
                    float v1 = acc[t][j][2*h+1] + bi.y; if (si.y == tv[ri]) v1 = -1.0e9f;
                    acc[t][j][2*h] = v0; acc[t][j][2*h+1] = v1;
                    bm = fmaxf(bm, fmaxf(v0, v1));
                }
                float nm = fmaxf(m[ri], bm);
                float s = l[ri] * __expf(m[ri] - nm);
                #pragma unroll
                for (int j=0;j<8;j++)
                    s += __expf(acc[t][j][2*h] - nm) + __expf(acc[t][j][2*h+1] - nm);
                l[ri] = s; m[ri] = nm;
            }
        }
    }

    // merge across the 4 lanes of each quad (same row, different cols)
    #pragma unroll
    for (int o=1; o<=2; o<<=1){
        #pragma unroll
        for (int i=0;i<4;i++){
            float om = __shfl_xor_sync(0xffffffffu, m[i], o);
            float ol = __shfl_xor_sync(0xffffffffu, l[i], o);
            float nm = fmaxf(m[i], om);
            l[i] = l[i]*__expf(m[i]-nm) + ol*__expf(om-nm);
            m[i] = nm;
        }
    }
    if ((lane & 3) == 0){
        #pragma unroll
        for (int i=0;i<4;i++){
            int t = i>>1, h = i&1;
            int row = m0 + t*16 + h*8 + (lane>>2);
            sMM[(warp & 1)*128 + row] = m[i];
            sLL[(warp & 1)*128 + row] = l[i];
        }
    }
    __syncthreads();
    if (tid < 128){
        float m0v = sMM[tid],     l0v = sLL[tid];
        float m1v = sMM[128+tid], l1v = sLL[128+tid];
        float nm = fmaxf(m0v, m1v);
        float L  = l0v*__expf(m0v-nm) + l1v*__expf(m1v-nm);
        float ta = g_trueAdj[b*SEQ + row0 + tid];
        float fm = fmaxf(nm, ta);
        float FL = L*__expf(nm-fm) + __expf(ta-fm);
        g_loss[b*SEQ + row0 + tid] = logf(FL) + fm - ta;
    }
}

// ---------------- mean ----------------
__global__ void k_final(float* out){
    __shared__ float ss[256];
    float s = 0.f;
    for (int i=threadIdx.x; i<BATCH*SEQ; i+=256) s += g_loss[i];
    ss[threadIdx.x] = s; __syncthreads();
    for (int o=128; o>0; o>>=1){
        if (threadIdx.x < o) ss[threadIdx.x] += ss[threadIdx.x + o];
        __syncthreads();
    }
    if (threadIdx.x == 0) out[0] = 0.5f * ss[0] / (float)(BATCH*SEQ);
}

extern "C" void kernel_launch(void* const* d_in, const int* in_sizes, int n_in,
                              void* d_out, int out_size){
    const float* X     = (const float*)d_in[0];
    const int*   nexts = (const int*)  d_in[1];
    const int*   samp  = (const int*)  d_in[2];
    const float* W     = (const float*)d_in[3];
    const float* bias  = (const float*)d_in[4];
    float* out = (float*)d_out;

    cudaFuncSetAttribute(k_main, cudaFuncAttributeMaxDynamicSharedMemorySize, SMEM_REQ);

    k_prep <<<4096 + 2048, 256>>>(X, nexts, samp, W, bias);
    k_main <<<BATCH*4, 256, SMEM_REQ>>>(nexts);
    k_final<<<1, 256>>>(out);
}

// round 5
// speedup vs baseline: 1.3319x; 1.0445x over previous
#include <cuda_runtime.h>
#include <cuda_bf16.h>
#include <cstdint>

#define BATCH 32
#define SEQ   512
#define DM    1024
#define NSAMP 1000
#define SPAD  1024
#define LDAH  136                 // smem row stride in halves (128 + 8 pad)
#define STAGE_BYTES 69632         // 256 rows * 136 halves * 2B (A:128 rows, B:128 rows)
#define NSTG  3
#define NIT   64                  // 8 nc * 8 kc(128)
#define OFF_BIAS (NSTG*STAGE_BYTES)       // 208896
#define OFF_SID  (OFF_BIAS + 4096)        // 212992
#define OFF_MM   (OFF_SID  + 4096)        // 217088  float[2][128]
#define OFF_LL   (OFF_MM   + 1024)        // 218112  float[2][128]
#define SMEM_REQ (OFF_LL + 1024)          // 219136

// ---------------- scratch (device globals; allocation-free rule) ----------------
__device__ __nv_bfloat16 g_Xbf[BATCH*SEQ*DM];
__device__ __nv_bfloat16 g_Wg [BATCH*SPAD*DM];
__device__ float g_biasAdj[BATCH*SPAD];
__device__ int   g_sid   [BATCH*SPAD];
__device__ float g_trueAdj[BATCH*SEQ];
__device__ float g_loss  [BATCH*SEQ];

__device__ __forceinline__ float log_q_f(int id){
    float f = (float)id;
    float p = (logf(f + 2.0f) - logf(f + 1.0f)) / 10.819798284210285f; // log(50001)
    float t = 1000.0f * log1pf(-p);
    return logf(-expm1f(t));
}

// ---------------- prelude: gather W rows -> bf16  +  exact f32 true logits + X->bf16 ----------------
__global__ void k_prep(const float* __restrict__ X, const int* __restrict__ nexts,
                       const int* __restrict__ samp, const float* __restrict__ W,
                       const float* __restrict__ bias){
    int lane = threadIdx.x & 31;
    if (blockIdx.x < 4096){
        int warp = (blockIdx.x*blockDim.x + threadIdx.x) >> 5;
        int b = warp >> 10, s = warp & 1023;
        int id = (s < NSAMP) ? samp[b*NSAMP + s] : -1;
        __nv_bfloat16* dst = g_Wg + (size_t)warp*DM;
        if (id >= 0){
            const float4* src = (const float4*)(W + (size_t)id*DM);
            #pragma unroll
            for (int j=0;j<8;j++){
                float4 v = src[lane + j*32];
                __nv_bfloat162 p0 = __floats2bfloat162_rn(v.x, v.y);
                __nv_bfloat162 p1 = __floats2bfloat162_rn(v.z, v.w);
                uint2 u; u.x = *(uint32_t*)&p0; u.y = *(uint32_t*)&p1;
                ((uint2*)dst)[lane + j*32] = u;
            }
            if (lane == 0){ g_biasAdj[warp] = bias[id] - log_q_f(id); g_sid[warp] = id; }
        } else {
            uint2 z = make_uint2(0u,0u);
            #pragma unroll
            for (int j=0;j<8;j++) ((uint2*)dst)[lane + j*32] = z;
            if (lane == 0){ g_biasAdj[warp] = -1.0e30f; g_sid[warp] = -1; }
        }
    } else {
        int g = (blockIdx.x - 4096)*8 + (threadIdx.x >> 5);
        int id = nexts[g];
        const float4* xr = (const float4*)(X + (size_t)g*DM);
        const float4* wr = (const float4*)(W + (size_t)id*DM);
        uint2* xo = (uint2*)(g_Xbf + (size_t)g*DM);
        float acc = 0.f;
        #pragma unroll
        for (int j=0;j<8;j++){
            float4 a = xr[lane + j*32], w = wr[lane + j*32];
            acc += a.x*w.x + a.y*w.y + a.z*w.z + a.w*w.w;
            __nv_bfloat162 p0 = __floats2bfloat162_rn(a.x, a.y);
            __nv_bfloat162 p1 = __floats2bfloat162_rn(a.z, a.w);
            uint2 u; u.x = *(uint32_t*)&p0; u.y = *(uint32_t*)&p1;
            xo[lane + j*32] = u;
        }
        #pragma unroll
        for (int off=16; off>0; off>>=1) acc += __shfl_xor_sync(0xffffffffu, acc, off);
        if (lane == 0) g_trueAdj[g] = acc + bias[id] - log_q_f(id);
    }
}

// ---------------- main: mma.sync GEMM + fragment-local online logsumexp ----------------
// grid 128 (4 CTAs/batch, M=128). 8 warps, 4x2 warp grid of 32x64 tiles, N-chunk=128,
// K-chunk=128, 3-stage cp.async ring, fragment double buffering inside a stage.
__device__ __forceinline__ void issue_stage(uint32_t sbase, int it,
    const __nv_bfloat16* Ag, const __nv_bfloat16* Bb,
    uint32_t dA, uint32_t dB, int r, int c8){
    if (it < NIT){
        int nc = it >> 3, kc = it & 7;
        uint32_t st = sbase + (uint32_t)(it % NSTG)*STAGE_BYTES;
        const __nv_bfloat16* gA = Ag + kc*128 + (size_t)r*DM + c8*8;
        const __nv_bfloat16* gB = Bb + (size_t)(nc*128 + r)*DM + kc*128 + c8*8;
        #pragma unroll
        for (int i=0;i<8;i++){
            asm volatile("cp.async.cg.shared.global [%0],[%1],16;"
                :: "r"(st + dA + (uint32_t)(i*16*(LDAH*2))), "l"(gA + (size_t)(i*16)*DM));
            asm volatile("cp.async.cg.shared.global [%0],[%1],16;"
                :: "r"(st + dB + (uint32_t)(i*16*(LDAH*2))), "l"(gB + (size_t)(i*16)*DM));
        }
    }
    asm volatile("cp.async.commit_group;");
}

__device__ __forceinline__ void load_frag(const __nv_bfloat16* A, const __nv_bfloat16* B,
    int m0, int n0, int lane, int kk, uint32_t (&af)[2][4], uint32_t (&bf)[8][2]){
    #pragma unroll
    for (int t=0;t<2;t++){
        const __nv_bfloat16* q = A + (m0 + t*16 + (lane & 15))*LDAH + kk*16 + (lane >> 4)*8;
        uint32_t sa = (uint32_t)__cvta_generic_to_shared(q);
        asm volatile("ldmatrix.sync.aligned.m8n8.x4.shared.b16 {%0,%1,%2,%3},[%4];"
            : "=r"(af[t][0]), "=r"(af[t][1]), "=r"(af[t][2]), "=r"(af[t][3]) : "r"(sa));
    }
    #pragma unroll
    for (int j=0;j<8;j+=2){
        const __nv_bfloat16* q = B + (n0 + j*8 + (lane & 7) + (lane >> 4)*8)*LDAH
                                   + kk*16 + ((lane >> 3) & 1)*8;
        uint32_t sb = (uint32_t)__cvta_generic_to_shared(q);
        asm volatile("ldmatrix.sync.aligned.m8n8.x4.shared.b16 {%0,%1,%2,%3},[%4];"
            : "=r"(bf[j][0]), "=r"(bf[j][1]), "=r"(bf[j+1][0]), "=r"(bf[j+1][1]) : "r"(sb));
    }
}

__global__ __launch_bounds__(256,1)
void k_main(const int* __restrict__ nexts){
    extern __shared__ char smraw[];
    char* p = smraw;
    const uint32_t sbase = (uint32_t)__cvta_generic_to_shared(p);
    float* sBias = (float*)(p + OFF_BIAS);
    int*   sSid  = (int*)  (p + OFF_SID);
    float* sMM   = (float*)(p + OFF_MM);
    float* sLL   = (float*)(p + OFF_LL);

    int tid = threadIdx.x, warp = tid >> 5, lane = tid & 31;
    int cta = blockIdx.x, b = cta >> 2, row0 = (cta & 3) << 7;
    int m0 = (warp >> 1) * 32, n0 = (warp & 1) * 64;

    // per-thread cp.async coordinates: 2048 16B chunks per matrix, 8 per thread
    int r = tid >> 4, c8 = tid & 15;   // r in [0,16), row step 16
    uint32_t dA = (uint32_t)(r*(LDAH*2) + c8*16);
    uint32_t dB = dA + (uint32_t)(128*(LDAH*2));

    for (int i=tid; i<SPAD; i+=256){ sBias[i] = g_biasAdj[b*SPAD+i]; sSid[i] = g_sid[b*SPAD+i]; }

    const __nv_bfloat16* Ag = g_Xbf + (size_t)(b*SEQ + row0)*DM;
    const __nv_bfloat16* Bb = g_Wg  + (size_t)b*SPAD*DM;

    int tv[4];
    #pragma unroll
    for (int i=0;i<4;i++){
        int t = i>>1, h = i&1;
        tv[i] = nexts[b*SEQ + row0 + m0 + t*16 + h*8 + (lane>>2)];
    }
    float m[4], l[4];
    #pragma unroll
    for (int i=0;i<4;i++){ m[i] = -3.0e38f; l[i] = 0.f; }

    issue_stage(sbase, 0, Ag, Bb, dA, dB, r, c8);
    issue_stage(sbase, 1, Ag, Bb, dA, dB, r, c8);

    float acc[2][8][4];
    uint32_t af[2][2][4], bf[2][8][2];

    for (int it=0; it<NIT; ++it){
        int nc = it >> 3, kc = it & 7;
        asm volatile("cp.async.wait_group 1;");
        __syncthreads();
        issue_stage(sbase, it+2, Ag, Bb, dA, dB, r, c8);

        if (kc == 0){
            #pragma unroll
            for (int t=0;t<2;t++)
            #pragma unroll
            for (int j=0;j<8;j++)
            #pragma unroll
            for (int k=0;k<4;k++) acc[t][j][k] = 0.f;
        }

        char* st = p + (it % NSTG)*STAGE_BYTES;
        const __nv_bfloat16* A = (const __nv_bfloat16*)st;
        const __nv_bfloat16* B = (const __nv_bfloat16*)(st + 128*LDAH*2);

        load_frag(A, B, m0, n0, lane, 0, af[0], bf[0]);
        #pragma unroll
        for (int kk=0; kk<8; kk++){
            int pb = kk & 1;
            if (kk < 7) load_frag(A, B, m0, n0, lane, kk+1, af[pb^1], bf[pb^1]);
            #pragma unroll
            for (int t=0;t<2;t++)
            #pragma unroll
            for (int j=0;j<8;j++){
                asm volatile("mma.sync.aligned.m16n8k16.row.col.f32.bf16.bf16.f32 "
                    "{%0,%1,%2,%3},{%4,%5,%6,%7},{%8,%9},{%0,%1,%2,%3};"
                    : "+f"(acc[t][j][0]), "+f"(acc[t][j][1]), "+f"(acc[t][j][2]), "+f"(acc[t][j][3])
                    : "r"(af[pb][t][0]), "r"(af[pb][t][1]), "r"(af[pb][t][2]), "r"(af[pb][t][3]),
                      "r"(bf[pb][j][0]), "r"(bf[pb][j][1]));
            }
        }

        if (kc == 7){
            int cbase = nc*128 + n0 + (lane & 3)*2;
            #pragma unroll
            for (int t=0;t<2;t++)
            #pragma unroll
            for (int h=0;h<2;h++){
                int ri = t*2 + h;
                float bm = -3.0e38f;
                #pragma unroll
                for (int j=0;j<8;j++){
                    int c = cbase + j*8;
                    float2 bi = *(const float2*)&sBias[c];
                    int2   si = *(const int2*)  &sSid[c];
                    float v0 = acc[t][j][2*h]   + bi.x; if (si.x == tv[ri]) v0 = -1.0e9f;
                    float v1 = acc[t][j][2*h+1] + bi.y; if (si.y == tv[ri]) v1 = -1.0e9f;
                    acc[t][j][2*h] = v0; acc[t][j][2*h+1] = v1;
                    bm = fmaxf(bm, fmaxf(v0, v1));
                }
                float nm = fmaxf(m[ri], bm);
                float s = l[ri] * __expf(m[ri] - nm);
                #pragma unroll
                for (int j=0;j<8;j++)
                    s += __expf(acc[t][j][2*h] - nm) + __expf(acc[t][j][2*h+1] - nm);
                l[ri] = s; m[ri] = nm;
            }
        }
    }

    // merge across the 4 lanes of each quad (same row, different cols)
    #pragma unroll
    for (int o=1; o<=2; o<<=1){
        #pragma unroll
        for (int i=0;i<4;i++){
            float om = __shfl_xor_sync(0xffffffffu, m[i], o);
            float ol = __shfl_xor_sync(0xffffffffu, l[i], o);
            float nm = fmaxf(m[i], om);
            l[i] = l[i]*__expf(m[i]-nm) + ol*__expf(om-nm);
            m[i] = nm;
        }
    }
    if ((lane & 3) == 0){
        #pragma unroll
        for (int i=0;i<4;i++){
            int t = i>>1, h = i&1;
            int row = m0 + t*16 + h*8 + (lane>>2);
            sMM[(warp & 1)*128 + row] = m[i];
            sLL[(warp & 1)*128 + row] = l[i];
        }
    }
    __syncthreads();
    if (tid < 128){
        float m0v = sMM[tid],     l0v = sLL[tid];
        float m1v = sMM[128+tid], l1v = sLL[128+tid];
        float nm = fmaxf(m0v, m1v);
        float L  = l0v*__expf(m0v-nm) + l1v*__expf(m1v-nm);
        float ta = g_trueAdj[b*SEQ + row0 + tid];
        float fm = fmaxf(nm, ta);
        float FL = L*__expf(nm-fm) + __expf(ta-fm);
        g_loss[b*SEQ + row0 + tid] = logf(FL) + fm - ta;
    }
}

// ---------------- mean ----------------
__global__ void k_final(float* out){
    __shared__ float ss[256];
    float s = 0.f;
    for (int i=threadIdx.x; i<BATCH*SEQ; i+=256) s += g_loss[i];
    ss[threadIdx.x] = s; __syncthreads();
    for (int o=128; o>0; o>>=1){
        if (threadIdx.x < o) ss[threadIdx.x] += ss[threadIdx.x + o];
        __syncthreads();
    }
    if (threadIdx.x == 0) out[0] = 0.5f * ss[0] / (float)(BATCH*SEQ);
}

extern "C" void kernel_launch(void* const* d_in, const int* in_sizes, int n_in,
                              void* d_out, int out_size){
    const float* X     = (const float*)d_in[0];
    const int*   nexts = (const int*)  d_in[1];
    const int*   samp  = (const int*)  d_in[2];
    const float* W     = (const float*)d_in[3];
    const float* bias  = (const float*)d_in[4];
    float* out = (float*)d_out;

    cudaFuncSetAttribute(k_main, cudaFuncAttributeMaxDynamicSharedMemorySize, SMEM_REQ);

    k_prep <<<4096 + 2048, 256>>>(X, nexts, samp, W, bias);
    k_main <<<BATCH*4, 256, SMEM_REQ>>>(nexts);
    k_final<<<1, 256>>>(out);
}

// round 10
// speedup vs baseline: 1.4555x; 1.0928x over previous
#include <cuda_runtime.h>
#include <cuda_bf16.h>
#include <cstdint>

#define BATCH 32
#define SEQ   512
#define DM    1024
#define NSAMP 1000
#define SPAD  1024
#define LDAH  136                        // smem row stride in halves (128 + 8 pad)
#define STAGE_BYTES ((128+256)*LDAH*2)   // 104448: A 128 rows + B 256 rows
#define NSTG  2
#define NIT   32                         // 4 nc * 8 kc
#define OFF_BIAS (NSTG*STAGE_BYTES)      // 208896
#define OFF_SID  (OFF_BIAS + 4096)       // 212992
#define OFF_MM   (OFF_SID  + 4096)       // 217088  float[4][128]
#define OFF_LL   (OFF_MM   + 2048)       // 219136  float[4][128]
#define SMEM_REQ (OFF_LL + 2048)         // 221184

// ---------------- scratch (device globals; allocation-free rule) ----------------
__device__ __nv_bfloat16 g_Xbf[BATCH*SEQ*DM];
__device__ __nv_bfloat16 g_Wg [BATCH*SPAD*DM];
__device__ float g_biasAdj[BATCH*SPAD];
__device__ int   g_sid   [BATCH*SPAD];
__device__ float g_trueAdj[BATCH*SEQ];
__device__ float g_loss  [BATCH*SEQ];

__device__ __forceinline__ float log_q_f(int id){
    float f = (float)id;
    float p = (logf(f + 2.0f) - logf(f + 1.0f)) / 10.819798284210285f; // log(50001)
    float t = 1000.0f * log1pf(-p);
    return logf(-expm1f(t));
}

// ---------------- prelude: gather W rows -> bf16  +  exact f32 true logits + X->bf16 ----------------
__global__ void k_prep(const float* __restrict__ X, const int* __restrict__ nexts,
                       const int* __restrict__ samp, const float* __restrict__ W,
                       const float* __restrict__ bias){
    int lane = threadIdx.x & 31;
    if (blockIdx.x < 4096){
        int warp = (blockIdx.x*blockDim.x + threadIdx.x) >> 5;
        int b = warp >> 10, s = warp & 1023;
        int id = (s < NSAMP) ? samp[b*NSAMP + s] : -1;
        __nv_bfloat16* dst = g_Wg + (size_t)warp*DM;
        if (id >= 0){
            const float4* src = (const float4*)(W + (size_t)id*DM);
            #pragma unroll
            for (int j=0;j<8;j++){
                float4 v = src[lane + j*32];
                __nv_bfloat162 p0 = __floats2bfloat162_rn(v.x, v.y);
                __nv_bfloat162 p1 = __floats2bfloat162_rn(v.z, v.w);
                uint2 u; u.x = *(uint32_t*)&p0; u.y = *(uint32_t*)&p1;
                ((uint2*)dst)[lane + j*32] = u;
            }
            if (lane == 0){ g_biasAdj[warp] = bias[id] - log_q_f(id); g_sid[warp] = id; }
        } else {
            uint2 z = make_uint2(0u,0u);
            #pragma unroll
            for (int j=0;j<8;j++) ((uint2*)dst)[lane + j*32] = z;
            if (lane == 0){ g_biasAdj[warp] = -1.0e30f; g_sid[warp] = -1; }
        }
    } else {
        int g = (blockIdx.x - 4096)*8 + (threadIdx.x >> 5);
        int id = nexts[g];
        const float4* xr = (const float4*)(X + (size_t)g*DM);
        const float4* wr = (const float4*)(W + (size_t)id*DM);
        uint2* xo = (uint2*)(g_Xbf + (size_t)g*DM);
        float acc = 0.f;
        #pragma unroll
        for (int j=0;j<8;j++){
            float4 a = xr[lane + j*32], w = wr[lane + j*32];
            acc += a.x*w.x + a.y*w.y + a.z*w.z + a.w*w.w;
            __nv_bfloat162 p0 = __floats2bfloat162_rn(a.x, a.y);
            __nv_bfloat162 p1 = __floats2bfloat162_rn(a.z, a.w);
            uint2 u; u.x = *(uint32_t*)&p0; u.y = *(uint32_t*)&p1;
            xo[lane + j*32] = u;
        }
        #pragma unroll
        for (int off=16; off>0; off>>=1) acc += __shfl_xor_sync(0xffffffffu, acc, off);
        if (lane == 0) g_trueAdj[g] = acc + bias[id] - log_q_f(id);
    }
}

// ---------------- main: mma.sync GEMM, 64x64 warp tiles, fused online logsumexp ----------------
// grid 128 (4 CTAs/batch, M=128). 8 warps in a 2(M)x4(N) grid of 64x64 tiles.
// N-chunk=256 (nc=0..3), K-chunk=128 (kc=0..7), 2-stage cp.async double buffer.
__device__ __forceinline__ void issue_stage(uint32_t sbase, int it,
    const __nv_bfloat16* Ag, const __nv_bfloat16* Bb, int tid){
    if (it < NIT){
        int nc = it >> 3, kc = it & 7;
        uint32_t st = sbase + (uint32_t)(it & 1)*STAGE_BYTES;
        int rb = tid >> 4, c8 = tid & 15;
        uint32_t d0 = st + (uint32_t)(rb*(LDAH*2) + c8*16);
        const __nv_bfloat16* gA = Ag + (size_t)rb*DM + kc*128 + c8*8;
        const __nv_bfloat16* gB = Bb + (size_t)(nc*256 + rb)*DM + kc*128 + c8*8;
        #pragma unroll
        for (int i=0;i<8;i++)
            asm volatile("cp.async.cg.shared.global [%0],[%1],16;"
                :: "r"(d0 + (uint32_t)(i*16*(LDAH*2))), "l"(gA + (size_t)(i*16)*DM));
        uint32_t d1 = d0 + (uint32_t)(128*(LDAH*2));
        #pragma unroll
        for (int i=0;i<16;i++)
            asm volatile("cp.async.cg.shared.global [%0],[%1],16;"
                :: "r"(d1 + (uint32_t)(i*16*(LDAH*2))), "l"(gB + (size_t)(i*16)*DM));
    }
    asm volatile("cp.async.commit_group;");
}

__global__ __launch_bounds__(256,1)
void k_main(const int* __restrict__ nexts){
    extern __shared__ char smraw[];
    char* p = smraw;
    const uint32_t sbase = (uint32_t)__cvta_generic_to_shared(p);
    float* sBias = (float*)(p + OFF_BIAS);
    int*   sSid  = (int*)  (p + OFF_SID);
    float* sMM   = (float*)(p + OFF_MM);
    float* sLL   = (float*)(p + OFF_LL);

    int tid = threadIdx.x, warp = tid >> 5, lane = tid & 31;
    int cta = blockIdx.x, b = cta >> 2, row0 = (cta & 3) << 7;
    int m0 = (warp >> 2) * 64, n0 = (warp & 3) * 64;

    for (int i=tid; i<SPAD; i+=256){ sBias[i] = g_biasAdj[b*SPAD+i]; sSid[i] = g_sid[b*SPAD+i]; }

    const __nv_bfloat16* Ag = g_Xbf + (size_t)(b*SEQ + row0)*DM;
    const __nv_bfloat16* Bb = g_Wg  + (size_t)b*SPAD*DM;

    int tv[8];
    #pragma unroll
    for (int mi=0;mi<4;mi++)
    #pragma unroll
    for (int h=0;h<2;h++)
        tv[mi*2+h] = nexts[b*SEQ + row0 + m0 + mi*16 + h*8 + (lane>>2)];
    float m[8], l[8];
    #pragma unroll
    for (int i=0;i<8;i++){ m[i] = -3.0e38f; l[i] = 0.f; }

    issue_stage(sbase, 0, Ag, Bb, tid);

    float acc[4][8][4];
    for (int it=0; it<NIT; ++it){
        int nc = it >> 3, kc = it & 7;
        asm volatile("cp.async.wait_group 0;");
        __syncthreads();
        issue_stage(sbase, it+1, Ag, Bb, tid);

        if (kc == 0){
            #pragma unroll
            for (int mi=0;mi<4;mi++)
            #pragma unroll
            for (int j=0;j<8;j++)
            #pragma unroll
            for (int k=0;k<4;k++) acc[mi][j][k] = 0.f;
        }

        char* st = p + (it & 1)*STAGE_BYTES;
        const __nv_bfloat16* A = (const __nv_bfloat16*)st;
        const __nv_bfloat16* B = (const __nv_bfloat16*)(st + 128*LDAH*2);

        #pragma unroll
        for (int kk=0; kk<8; kk++){
            uint32_t af[4][4];
            #pragma unroll
            for (int mi=0;mi<4;mi++){
                const __nv_bfloat16* q = A + (m0 + mi*16 + (lane & 15))*LDAH + kk*16 + (lane >> 4)*8;
                uint32_t sa = (uint32_t)__cvta_generic_to_shared(q);
                asm volatile("ldmatrix.sync.aligned.m8n8.x4.shared.b16 {%0,%1,%2,%3},[%4];"
                    : "=r"(af[mi][0]), "=r"(af[mi][1]), "=r"(af[mi][2]), "=r"(af[mi][3]) : "r"(sa));
            }
            uint32_t bf[8][2];
            #pragma unroll
            for (int j=0;j<8;j+=2){
                const __nv_bfloat16* q = B + (n0 + j*8 + (lane & 7) + (lane >> 4)*8)*LDAH
                                           + kk*16 + ((lane >> 3) & 1)*8;
                uint32_t sb = (uint32_t)__cvta_generic_to_shared(q);
                asm volatile("ldmatrix.sync.aligned.m8n8.x4.shared.b16 {%0,%1,%2,%3},[%4];"
                    : "=r"(bf[j][0]), "=r"(bf[j][1]), "=r"(bf[j+1][0]), "=r"(bf[j+1][1]) : "r"(sb));
            }
            #pragma unroll
            for (int mi=0;mi<4;mi++)
            #pragma unroll
            for (int j=0;j<8;j++){
                asm volatile("mma.sync.aligned.m16n8k16.row.col.f32.bf16.bf16.f32 "
                    "{%0,%1,%2,%3},{%4,%5,%6,%7},{%8,%9},{%0,%1,%2,%3};"
                    : "+f"(acc[mi][j][0]), "+f"(acc[mi][j][1]), "+f"(acc[mi][j][2]), "+f"(acc[mi][j][3])
                    : "r"(af[mi][0]), "r"(af[mi][1]), "r"(af[mi][2]), "r"(af[mi][3]),
                      "r"(bf[j][0]), "r"(bf[j][1]));
            }
        }

        if (kc == 7){
            int cb = nc*256 + n0 + (lane & 3)*2;
            float2 bi[8]; int2 si[8];
            #pragma unroll
            for (int j=0;j<8;j++){
                bi[j] = *(const float2*)&sBias[cb + j*8];
                si[j] = *(const int2*)  &sSid [cb + j*8];
            }
            #pragma unroll
            for (int mi=0;mi<4;mi++)
            #pragma unroll
            for (int h=0;h<2;h++){
                int ri = mi*2 + h;
                float bm = -3.0e38f;
                #pragma unroll
                for (int j=0;j<8;j++){
                    float v0 = acc[mi][j][2*h]   + bi[j].x; if (si[j].x == tv[ri]) v0 = -1.0e9f;
                    float v1 = acc[mi][j][2*h+1] + bi[j].y; if (si[j].y == tv[ri]) v1 = -1.0e9f;
                    acc[mi][j][2*h] = v0; acc[mi][j][2*h+1] = v1;
                    bm = fmaxf(bm, fmaxf(v0, v1));
                }
                float nm = fmaxf(m[ri], bm);
                float s = l[ri] * __expf(m[ri] - nm);
                #pragma unroll
                for (int j=0;j<8;j++)
                    s += __expf(acc[mi][j][2*h] - nm) + __expf(acc[mi][j][2*h+1] - nm);
                l[ri] = s; m[ri] = nm;
            }
        }
    }

    // merge across the 4 lanes of each quad (same rows, different cols)
    #pragma unroll
    for (int o=1; o<=2; o<<=1){
        #pragma unroll
        for (int i=0;i<8;i++){
            float om = __shfl_xor_sync(0xffffffffu, m[i], o);
            float ol = __shfl_xor_sync(0xffffffffu, l[i], o);
            float nm = fmaxf(m[i], om);
            l[i] = l[i]*__expf(m[i]-nm) + ol*__expf(om-nm);
            m[i] = nm;
        }
    }
    if ((lane & 3) == 0){
        #pragma unroll
        for (int mi=0;mi<4;mi++)
        #pragma unroll
        for (int h=0;h<2;h++){
            int row = m0 + mi*16 + h*8 + (lane>>2);
            sMM[(warp & 3)*128 + row] = m[mi*2+h];
            sLL[(warp & 3)*128 + row] = l[mi*2+h];
        }
    }
    __syncthreads();
    if (tid < 128){
        float M0 = sMM[tid],       L0 = sLL[tid];
        float M1 = sMM[128+tid],   L1 = sLL[128+tid];
        float M2 = sMM[256+tid],   L2 = sLL[256+tid];
        float M3 = sMM[384+tid],   L3 = sLL[384+tid];
        float nm = fmaxf(fmaxf(M0,M1), fmaxf(M2,M3));
        float L  = L0*__expf(M0-nm) + L1*__expf(M1-nm) + L2*__expf(M2-nm) + L3*__expf(M3-nm);
        float ta = g_trueAdj[b*SEQ + row0 + tid];
        float fm = fmaxf(nm, ta);
        float FL = L*__expf(nm-fm) + __expf(ta-fm);
        g_loss[b*SEQ + row0 + tid] = logf(FL) + fm - ta;
    }
}

// ---------------- mean ----------------
__global__ void k_final(float* out){
    __shared__ float ss[256];
    float s = 0.f;
    for (int i=threadIdx.x; i<BATCH*SEQ; i+=256) s += g_loss[i];
    ss[threadIdx.x] = s; __syncthreads();
    for (int o=128; o>0; o>>=1){
        if (threadIdx.x < o) ss[threadIdx.x] += ss[threadIdx.x + o];
        __syncthreads();
    }
    if (threadIdx.x == 0) out[0] = 0.5f * ss[0] / (float)(BATCH*SEQ);
}

extern "C" void kernel_launch(void* const* d_in, const int* in_sizes, int n_in,
                              void* d_out, int out_size){
    const float* X     = (const float*)d_in[0];
    const int*   nexts = (const int*)  d_in[1];
    const int*   samp  = (const int*)  d_in[2];
    const float* W     = (const float*)d_in[3];
    const float* bias  = (const float*)d_in[4];
    float* out = (float*)d_out;

    cudaFuncSetAttribute(k_main, cudaFuncAttributeMaxDynamicSharedMemorySize, SMEM_REQ);

    k_prep <<<4096 + 2048, 256>>>(X, nexts, samp, W, bias);
    k_main <<<BATCH*4, 256, SMEM_REQ>>>(nexts);
    k_final<<<1, 256>>>(out);
}